// round 5
// baseline (speedup 1.0000x reference)
#include <cuda_runtime.h>
#include <utility>
#include <cstddef>

// ============================================================================
// Compile-time construction of the e3nn real Wigner-3j sparse metadata.
// Mirrors the reference numpy code exactly, in double precision constexpr.
// ============================================================================

#define LMAX     3
#define DIM_IN   16
#define DIM_OUT  99
#define CHANNELS 128
#define MAXE     1400

struct Meta {
    int   n;        // number of nonzero entries
    int   out_dim;  // sanity: must equal 99
    short i1[MAXE]; // index into x irrep dim (0..15)
    short i2[MAXE]; // index into y irrep dim (0..15)
    short i3[MAXE]; // index into out irrep dim (0..98)
    float v[MAXE];  // cg value (path-weighted, frobenius-normalized)
};

__host__ __device__ constexpr double cfact(int n) {
    double r = 1.0;
    for (int i = 2; i <= n; i++) r *= (double)i;
    return r;
}

__host__ __device__ constexpr double csqrt(double x) {
    if (x <= 0.0) return 0.0;
    double r = x > 1.0 ? x : 1.0;
    for (int i = 0; i < 60; i++) r = 0.5 * (r + x / r);
    return r;
}

__host__ __device__ constexpr int imax2(int a, int b) { return a > b ? a : b; }
__host__ __device__ constexpr int imin2(int a, int b) { return a < b ? a : b; }

// SU(2) Clebsch-Gordan coefficient (same formula as reference _cg_coef)
__host__ __device__ constexpr double cg_coef(int j1, int m1, int j2, int m2,
                                             int j3, int m3) {
    if (m3 != m1 + m2) return 0.0;
    int vmin = imax2(imax2(-j1 + j2 + m3, -j1 + m1), 0);
    int vmax = imin2(imin2(j2 + j3 + m1, j3 - j1 + j2), j3 + m3);
    double C = csqrt((2.0 * j3 + 1.0)
        * cfact(j3 + j1 - j2) * cfact(j3 - j1 + j2) * cfact(j1 + j2 - j3)
        / cfact(j1 + j2 + j3 + 1)
        * cfact(j3 + m3) * cfact(j3 - m3)
        / (cfact(j1 + m1) * cfact(j1 - m1) * cfact(j2 + m2) * cfact(j2 - m2)));
    double S = 0.0;
    for (int v = vmin; v <= vmax; v++) {
        double sgn = ((v + j2 + m2) & 1) ? -1.0 : 1.0;
        S += sgn * cfact(j2 + j3 + m1 - v) * cfact(j1 - m1 + v)
             / (cfact(v) * cfact(j3 - j1 + j2 - v) * cfact(j3 + m3 - v)
                * cfact(v + j1 - j2 - m3));
    }
    return C * S;
}

struct Cpx { double re; double im; };
__host__ __device__ constexpr Cpx cmul(Cpx a, Cpx b) {
    return Cpx{a.re * b.re - a.im * b.im, a.re * b.im + a.im * b.re};
}

// Row l+m of q(l) (real -> complex SH basis change, e3nn convention),
// including the (-1j)^l global phase. Each row has <= 2 nonzeros.
struct QRow { int ncol; int col[2]; Cpx val[2]; };

__host__ __device__ constexpr QRow qrow(int l, int m) {
    QRow r{};
    double inv2 = 1.0 / csqrt(2.0);
    if (m < 0) {
        r.ncol = 2;
        r.col[0] = l - m;  r.val[0] = Cpx{ inv2, 0.0 };   // l + |m|
        r.col[1] = l + m;  r.val[1] = Cpx{ 0.0, -inv2 };  // l - |m|
    } else if (m == 0) {
        r.ncol = 1;
        r.col[0] = l;      r.val[0] = Cpx{ 1.0, 0.0 };
    } else {
        double s = (m & 1) ? -1.0 : 1.0;  // (-1)^m
        r.ncol = 2;
        r.col[0] = l + m;  r.val[0] = Cpx{ s * inv2, 0.0 };
        r.col[1] = l - m;  r.val[1] = Cpx{ 0.0, s * inv2 };
    }
    // phase (-1j)^l
    Cpx p = (l % 4 == 0) ? Cpx{1, 0} : (l % 4 == 1) ? Cpx{0, -1}
          : (l % 4 == 2) ? Cpx{-1, 0} : Cpx{0, 1};
    for (int t = 0; t < r.ncol; t++) r.val[t] = cmul(p, r.val[t]);
    return r;
}

__host__ __device__ constexpr Meta build_meta() {
    Meta M{};
    M.n = 0;
    int out_off = 0;
    for (int l1 = 0; l1 <= LMAX; l1++) {
        for (int l2 = 0; l2 <= LMAX; l2++) {
            int lo = (l1 > l2) ? (l1 - l2) : (l2 - l1);
            for (int l3 = lo; l3 <= l1 + l2; l3++) {
                if (l3 > LMAX) continue;
                // parity: (-1)^l1 * (-1)^l2 == (-1)^l3  <=>  l1+l2+l3 even
                if (((l1 + l2 + l3) & 1) != 0) continue;

                // real-basis CG tensor:
                // C[a][b][c] = sum_{m1,m2} q1[i,a] q2[k,b] conj(q3[n,c]) * cg
                Cpx Cc[7][7][7] = {};
                for (int m1 = -l1; m1 <= l1; m1++) {
                    for (int m2 = -l2; m2 <= l2; m2++) {
                        int m3 = m1 + m2;
                        if (m3 < -l3 || m3 > l3) continue;
                        double cg = cg_coef(l1, m1, l2, m2, l3, m3);
                        if (cg == 0.0) continue;
                        QRow r1 = qrow(l1, m1);
                        QRow r2 = qrow(l2, m2);
                        QRow r3 = qrow(l3, m3);
                        for (int a = 0; a < r1.ncol; a++)
                        for (int b = 0; b < r2.ncol; b++)
                        for (int c = 0; c < r3.ncol; c++) {
                            Cpx t = cmul(r1.val[a], r2.val[b]);
                            Cpx q3c = Cpx{ r3.val[c].re, -r3.val[c].im };
                            t = cmul(t, q3c);
                            Cc[r1.col[a]][r2.col[b]][r3.col[c]].re += t.re * cg;
                            Cc[r1.col[a]][r2.col[b]][r3.col[c]].im += t.im * cg;
                        }
                    }
                }
                // frobenius-normalize (real part), apply path weight sqrt(2l3+1)
                double nrm2 = 0.0;
                for (int a = 0; a < 2 * l1 + 1; a++)
                for (int b = 0; b < 2 * l2 + 1; b++)
                for (int c = 0; c < 2 * l3 + 1; c++)
                    nrm2 += Cc[a][b][c].re * Cc[a][b][c].re;
                double scale = csqrt((2.0 * l3 + 1.0) / nrm2);

                for (int a = 0; a < 2 * l1 + 1; a++)
                for (int b = 0; b < 2 * l2 + 1; b++)
                for (int c = 0; c < 2 * l3 + 1; c++) {
                    double v = Cc[a][b][c].re * scale;
                    if (v > 1e-12 || v < -1e-12) {
                        if (M.n < MAXE) {
                            M.i1[M.n] = (short)(l1 * l1 + a);
                            M.i2[M.n] = (short)(l2 * l2 + b);
                            M.i3[M.n] = (short)(out_off + c);
                            M.v[M.n]  = (float)v;
                        }
                        M.n++;
                    }
                }
                out_off += 2 * l3 + 1;
            }
        }
    }
    M.out_dim = out_off;
    return M;
}

// Single shared compile-time metadata instance. Device code touches it ONLY
// inside constexpr initializers / template arguments (constant expressions,
// no odr-use), so no --expt-relaxed-constexpr is needed and the struct is
// never materialized in device memory.
struct MetaHolder {
    static constexpr Meta M = build_meta();   // implicitly inline (C++17)
};
static_assert(MetaHolder::M.n > 0,              "empty metadata");
static_assert(MetaHolder::M.n <= MAXE,          "MAXE too small");
static_assert(MetaHolder::M.out_dim == DIM_OUT, "out_dim mismatch");

__host__ __device__ constexpr int meta_n() { return MetaHolder::M.n; }

// ============================================================================
// Front-end (template) unrolled contraction: every index and weight is a
// function-local constexpr scalar -> guaranteed literal in the emitted code.
// acc/xv/yv are only ever indexed by compile-time constants -> registers.
// ============================================================================

template<int K>
__device__ __forceinline__ void fma_one(const float (&xv)[DIM_IN],
                                        const float (&yv)[DIM_IN],
                                        float (&acc)[DIM_OUT]) {
    constexpr int   a = MetaHolder::M.i1[K];
    constexpr int   b = MetaHolder::M.i2[K];
    constexpr int   c = MetaHolder::M.i3[K];
    constexpr float w = MetaHolder::M.v[K];
    acc[c] = fmaf(w, xv[a] * yv[b], acc[c]);
}

template<std::size_t... Ks>
__device__ __forceinline__ void contract(std::index_sequence<Ks...>,
                                         const float (&xv)[DIM_IN],
                                         const float (&yv)[DIM_IN],
                                         float (&acc)[DIM_OUT]) {
    (fma_one<(int)Ks>(xv, yv, acc), ...);
}

template<std::size_t... Is>
__device__ __forceinline__ void load_all(std::index_sequence<Is...>,
                                         const float* __restrict__ xp,
                                         const float* __restrict__ yp,
                                         float (&xv)[DIM_IN],
                                         float (&yv)[DIM_IN]) {
    ((xv[Is] = xp[Is * CHANNELS]), ...);
    ((yv[Is] = yp[Is * CHANNELS]), ...);
}

template<std::size_t... Js>
__device__ __forceinline__ void zero_all(std::index_sequence<Js...>,
                                         float (&acc)[DIM_OUT]) {
    ((acc[Js] = 0.0f), ...);
}

template<std::size_t... Js>
__device__ __forceinline__ void store_all(std::index_sequence<Js...>,
                                          float* __restrict__ op,
                                          const float (&acc)[DIM_OUT]) {
    ((op[Js * CHANNELS] = acc[Js]), ...);
}

// ============================================================================
// Kernel: one thread per (edge, channel). 512B coalesced rows; zero smem;
// no local memory; CG weights folded into FFMA immediates.
// ============================================================================

__global__ void __launch_bounds__(128, 2)
tp_kernel(const float* __restrict__ x, const float* __restrict__ y,
          float* __restrict__ out) {
    const int n = blockIdx.x;
    const int c = threadIdx.x;

    const float* xp = x + (size_t)n * DIM_IN * CHANNELS + c;
    const float* yp = y + (size_t)n * DIM_IN * CHANNELS + c;

    float xv[DIM_IN], yv[DIM_IN];
    load_all(std::make_index_sequence<DIM_IN>{}, xp, yp, xv, yv);

    float acc[DIM_OUT];
    zero_all(std::make_index_sequence<DIM_OUT>{}, acc);

    contract(std::make_index_sequence<meta_n()>{}, xv, yv, acc);

    float* op = out + (size_t)n * DIM_OUT * CHANNELS + c;
    store_all(std::make_index_sequence<DIM_OUT>{}, op, acc);
}

// ============================================================================
// Launch
// ============================================================================

extern "C" void kernel_launch(void* const* d_in, const int* in_sizes, int n_in,
                              void* d_out, int out_size) {
    const float* x = (const float*)d_in[0];
    const float* y = (const float*)d_in[1];
    // mu1/mu2/mu3/cg (d_in[2..5]) are fixed mathematical constants baked in
    // at compile time; ignored at runtime.
    float* out = (float*)d_out;

    int n_edges = in_sizes[0] / (DIM_IN * CHANNELS);
    tp_kernel<<<n_edges, CHANNELS>>>(x, y, out);
}

// round 6
// speedup vs baseline: 1.0136x; 1.0136x over previous
#include <cuda_runtime.h>
#include <utility>
#include <cstddef>

// ============================================================================
// Compile-time construction of the e3nn real Wigner-3j sparse metadata.
// Mirrors the reference numpy code exactly, in double precision constexpr.
// ============================================================================

#define LMAX     3
#define DIM_IN   16
#define DIM_OUT  99
#define CHANNELS 128
#define MAXE     1400

struct Meta {
    int   n;        // number of nonzero entries
    int   out_dim;  // sanity: must equal 99
    short i1[MAXE]; // index into x irrep dim (0..15)
    short i2[MAXE]; // index into y irrep dim (0..15)
    short i3[MAXE]; // index into out irrep dim (0..98)
    float v[MAXE];  // cg value (path-weighted, frobenius-normalized)
};

__host__ __device__ constexpr double cfact(int n) {
    double r = 1.0;
    for (int i = 2; i <= n; i++) r *= (double)i;
    return r;
}

__host__ __device__ constexpr double csqrt(double x) {
    if (x <= 0.0) return 0.0;
    double r = x > 1.0 ? x : 1.0;
    for (int i = 0; i < 60; i++) r = 0.5 * (r + x / r);
    return r;
}

__host__ __device__ constexpr int imax2(int a, int b) { return a > b ? a : b; }
__host__ __device__ constexpr int imin2(int a, int b) { return a < b ? a : b; }

// SU(2) Clebsch-Gordan coefficient (same formula as reference _cg_coef)
__host__ __device__ constexpr double cg_coef(int j1, int m1, int j2, int m2,
                                             int j3, int m3) {
    if (m3 != m1 + m2) return 0.0;
    int vmin = imax2(imax2(-j1 + j2 + m3, -j1 + m1), 0);
    int vmax = imin2(imin2(j2 + j3 + m1, j3 - j1 + j2), j3 + m3);
    double C = csqrt((2.0 * j3 + 1.0)
        * cfact(j3 + j1 - j2) * cfact(j3 - j1 + j2) * cfact(j1 + j2 - j3)
        / cfact(j1 + j2 + j3 + 1)
        * cfact(j3 + m3) * cfact(j3 - m3)
        / (cfact(j1 + m1) * cfact(j1 - m1) * cfact(j2 + m2) * cfact(j2 - m2)));
    double S = 0.0;
    for (int v = vmin; v <= vmax; v++) {
        double sgn = ((v + j2 + m2) & 1) ? -1.0 : 1.0;
        S += sgn * cfact(j2 + j3 + m1 - v) * cfact(j1 - m1 + v)
             / (cfact(v) * cfact(j3 - j1 + j2 - v) * cfact(j3 + m3 - v)
                * cfact(v + j1 - j2 - m3));
    }
    return C * S;
}

struct Cpx { double re; double im; };
__host__ __device__ constexpr Cpx cmul(Cpx a, Cpx b) {
    return Cpx{a.re * b.re - a.im * b.im, a.re * b.im + a.im * b.re};
}

// Row l+m of q(l) (real -> complex SH basis change, e3nn convention),
// including the (-1j)^l global phase. Each row has <= 2 nonzeros.
struct QRow { int ncol; int col[2]; Cpx val[2]; };

__host__ __device__ constexpr QRow qrow(int l, int m) {
    QRow r{};
    double inv2 = 1.0 / csqrt(2.0);
    if (m < 0) {
        r.ncol = 2;
        r.col[0] = l - m;  r.val[0] = Cpx{ inv2, 0.0 };   // l + |m|
        r.col[1] = l + m;  r.val[1] = Cpx{ 0.0, -inv2 };  // l - |m|
    } else if (m == 0) {
        r.ncol = 1;
        r.col[0] = l;      r.val[0] = Cpx{ 1.0, 0.0 };
    } else {
        double s = (m & 1) ? -1.0 : 1.0;  // (-1)^m
        r.ncol = 2;
        r.col[0] = l + m;  r.val[0] = Cpx{ s * inv2, 0.0 };
        r.col[1] = l - m;  r.val[1] = Cpx{ 0.0, s * inv2 };
    }
    // phase (-1j)^l
    Cpx p = (l % 4 == 0) ? Cpx{1, 0} : (l % 4 == 1) ? Cpx{0, -1}
          : (l % 4 == 2) ? Cpx{-1, 0} : Cpx{0, 1};
    for (int t = 0; t < r.ncol; t++) r.val[t] = cmul(p, r.val[t]);
    return r;
}

__host__ __device__ constexpr Meta build_meta() {
    Meta M{};
    M.n = 0;
    int out_off = 0;
    for (int l1 = 0; l1 <= LMAX; l1++) {
        for (int l2 = 0; l2 <= LMAX; l2++) {
            int lo = (l1 > l2) ? (l1 - l2) : (l2 - l1);
            for (int l3 = lo; l3 <= l1 + l2; l3++) {
                if (l3 > LMAX) continue;
                // parity: (-1)^l1 * (-1)^l2 == (-1)^l3  <=>  l1+l2+l3 even
                if (((l1 + l2 + l3) & 1) != 0) continue;

                // real-basis CG tensor:
                // C[a][b][c] = sum_{m1,m2} q1[i,a] q2[k,b] conj(q3[n,c]) * cg
                Cpx Cc[7][7][7] = {};
                for (int m1 = -l1; m1 <= l1; m1++) {
                    for (int m2 = -l2; m2 <= l2; m2++) {
                        int m3 = m1 + m2;
                        if (m3 < -l3 || m3 > l3) continue;
                        double cg = cg_coef(l1, m1, l2, m2, l3, m3);
                        if (cg == 0.0) continue;
                        QRow r1 = qrow(l1, m1);
                        QRow r2 = qrow(l2, m2);
                        QRow r3 = qrow(l3, m3);
                        for (int a = 0; a < r1.ncol; a++)
                        for (int b = 0; b < r2.ncol; b++)
                        for (int c = 0; c < r3.ncol; c++) {
                            Cpx t = cmul(r1.val[a], r2.val[b]);
                            Cpx q3c = Cpx{ r3.val[c].re, -r3.val[c].im };
                            t = cmul(t, q3c);
                            Cc[r1.col[a]][r2.col[b]][r3.col[c]].re += t.re * cg;
                            Cc[r1.col[a]][r2.col[b]][r3.col[c]].im += t.im * cg;
                        }
                    }
                }
                // frobenius-normalize (real part), apply path weight sqrt(2l3+1)
                double nrm2 = 0.0;
                for (int a = 0; a < 2 * l1 + 1; a++)
                for (int b = 0; b < 2 * l2 + 1; b++)
                for (int c = 0; c < 2 * l3 + 1; c++)
                    nrm2 += Cc[a][b][c].re * Cc[a][b][c].re;
                double scale = csqrt((2.0 * l3 + 1.0) / nrm2);

                for (int a = 0; a < 2 * l1 + 1; a++)
                for (int b = 0; b < 2 * l2 + 1; b++)
                for (int c = 0; c < 2 * l3 + 1; c++) {
                    double v = Cc[a][b][c].re * scale;
                    if (v > 1e-12 || v < -1e-12) {
                        if (M.n < MAXE) {
                            M.i1[M.n] = (short)(l1 * l1 + a);
                            M.i2[M.n] = (short)(l2 * l2 + b);
                            M.i3[M.n] = (short)(out_off + c);
                            M.v[M.n]  = (float)v;
                        }
                        M.n++;
                    }
                }
                out_off += 2 * l3 + 1;
            }
        }
    }
    M.out_dim = out_off;
    return M;
}

// Single shared compile-time metadata instance. Device code touches it ONLY
// inside constexpr initializers / template arguments (constant expressions,
// no odr-use), so no --expt-relaxed-constexpr is needed and the struct is
// never materialized in device memory.
struct MetaHolder {
    static constexpr Meta M = build_meta();   // implicitly inline (C++17)
};
static_assert(MetaHolder::M.n > 0,              "empty metadata");
static_assert(MetaHolder::M.n <= MAXE,          "MAXE too small");
static_assert(MetaHolder::M.out_dim == DIM_OUT, "out_dim mismatch");

__host__ __device__ constexpr int meta_n() { return MetaHolder::M.n; }

// ============================================================================
// Front-end (template) unrolled contraction: every index and weight is a
// function-local constexpr scalar -> guaranteed literal in the emitted code.
// acc/xv/yv are only ever indexed by compile-time constants -> registers.
// ============================================================================

template<int K>
__device__ __forceinline__ void fma_one(const float (&xv)[DIM_IN],
                                        const float (&yv)[DIM_IN],
                                        float (&acc)[DIM_OUT]) {
    constexpr int   a = MetaHolder::M.i1[K];
    constexpr int   b = MetaHolder::M.i2[K];
    constexpr int   c = MetaHolder::M.i3[K];
    constexpr float w = MetaHolder::M.v[K];
    acc[c] = fmaf(w, xv[a] * yv[b], acc[c]);
}

template<std::size_t... Ks>
__device__ __forceinline__ void contract(std::index_sequence<Ks...>,
                                         const float (&xv)[DIM_IN],
                                         const float (&yv)[DIM_IN],
                                         float (&acc)[DIM_OUT]) {
    (fma_one<(int)Ks>(xv, yv, acc), ...);
}

template<std::size_t... Is>
__device__ __forceinline__ void load_all(std::index_sequence<Is...>,
                                         const float* __restrict__ xp,
                                         const float* __restrict__ yp,
                                         float (&xv)[DIM_IN],
                                         float (&yv)[DIM_IN]) {
    // read-once data: streaming loads (evict-first), keep L2 for the writes
    ((xv[Is] = __ldcs(xp + Is * CHANNELS)), ...);
    ((yv[Is] = __ldcs(yp + Is * CHANNELS)), ...);
}

template<std::size_t... Js>
__device__ __forceinline__ void zero_all(std::index_sequence<Js...>,
                                         float (&acc)[DIM_OUT]) {
    ((acc[Js] = 0.0f), ...);
}

template<std::size_t... Js>
__device__ __forceinline__ void store_all(std::index_sequence<Js...>,
                                          float* __restrict__ op,
                                          const float (&acc)[DIM_OUT]) {
    // write-once, never re-read: streaming stores
    ((__stcs(op + Js * CHANNELS, acc[Js])), ...);
}

// ============================================================================
// Kernel: one thread per (edge, channel). 512B coalesced rows; zero smem;
// no local memory; CG weights folded into FFMA immediates.
// __launch_bounds__(128, 8): cap regs at 64 (current use: 56) and target
// 8 resident blocks / 32 warps per SM for memory-latency overlap.
// ============================================================================

__global__ void __launch_bounds__(128, 8)
tp_kernel(const float* __restrict__ x, const float* __restrict__ y,
          float* __restrict__ out) {
    const int n = blockIdx.x;
    const int c = threadIdx.x;

    const float* xp = x + (size_t)n * DIM_IN * CHANNELS + c;
    const float* yp = y + (size_t)n * DIM_IN * CHANNELS + c;

    float xv[DIM_IN], yv[DIM_IN];
    load_all(std::make_index_sequence<DIM_IN>{}, xp, yp, xv, yv);

    float acc[DIM_OUT];
    zero_all(std::make_index_sequence<DIM_OUT>{}, acc);

    contract(std::make_index_sequence<meta_n()>{}, xv, yv, acc);

    float* op = out + (size_t)n * DIM_OUT * CHANNELS + c;
    store_all(std::make_index_sequence<DIM_OUT>{}, op, acc);
}

// ============================================================================
// Launch
// ============================================================================

extern "C" void kernel_launch(void* const* d_in, const int* in_sizes, int n_in,
                              void* d_out, int out_size) {
    const float* x = (const float*)d_in[0];
    const float* y = (const float*)d_in[1];
    // mu1/mu2/mu3/cg (d_in[2..5]) are fixed mathematical constants baked in
    // at compile time; ignored at runtime.
    float* out = (float*)d_out;

    int n_edges = in_sizes[0] / (DIM_IN * CHANNELS);
    tp_kernel<<<n_edges, CHANNELS>>>(x, y, out);
}

// round 7
// speedup vs baseline: 1.0276x; 1.0138x over previous
#include <cuda_runtime.h>
#include <utility>
#include <cstddef>

// ============================================================================
// Compile-time construction of the e3nn real Wigner-3j sparse metadata.
// Mirrors the reference numpy code exactly, in double precision constexpr.
// ============================================================================

#define LMAX     3
#define DIM_IN   16
#define DIM_OUT  99
#define CHANNELS 128
#define MAXE     1400

struct Meta {
    int   n;        // number of nonzero entries
    int   out_dim;  // sanity: must equal 99
    short i1[MAXE]; // index into x irrep dim (0..15)
    short i2[MAXE]; // index into y irrep dim (0..15)
    short i3[MAXE]; // index into out irrep dim (0..98)
    float v[MAXE];  // cg value (path-weighted, frobenius-normalized)
};

__host__ __device__ constexpr double cfact(int n) {
    double r = 1.0;
    for (int i = 2; i <= n; i++) r *= (double)i;
    return r;
}

__host__ __device__ constexpr double csqrt(double x) {
    if (x <= 0.0) return 0.0;
    double r = x > 1.0 ? x : 1.0;
    for (int i = 0; i < 60; i++) r = 0.5 * (r + x / r);
    return r;
}

__host__ __device__ constexpr int imax2(int a, int b) { return a > b ? a : b; }
__host__ __device__ constexpr int imin2(int a, int b) { return a < b ? a : b; }

// SU(2) Clebsch-Gordan coefficient (same formula as reference _cg_coef)
__host__ __device__ constexpr double cg_coef(int j1, int m1, int j2, int m2,
                                             int j3, int m3) {
    if (m3 != m1 + m2) return 0.0;
    int vmin = imax2(imax2(-j1 + j2 + m3, -j1 + m1), 0);
    int vmax = imin2(imin2(j2 + j3 + m1, j3 - j1 + j2), j3 + m3);
    double C = csqrt((2.0 * j3 + 1.0)
        * cfact(j3 + j1 - j2) * cfact(j3 - j1 + j2) * cfact(j1 + j2 - j3)
        / cfact(j1 + j2 + j3 + 1)
        * cfact(j3 + m3) * cfact(j3 - m3)
        / (cfact(j1 + m1) * cfact(j1 - m1) * cfact(j2 + m2) * cfact(j2 - m2)));
    double S = 0.0;
    for (int v = vmin; v <= vmax; v++) {
        double sgn = ((v + j2 + m2) & 1) ? -1.0 : 1.0;
        S += sgn * cfact(j2 + j3 + m1 - v) * cfact(j1 - m1 + v)
             / (cfact(v) * cfact(j3 - j1 + j2 - v) * cfact(j3 + m3 - v)
                * cfact(v + j1 - j2 - m3));
    }
    return C * S;
}

struct Cpx { double re; double im; };
__host__ __device__ constexpr Cpx cmul(Cpx a, Cpx b) {
    return Cpx{a.re * b.re - a.im * b.im, a.re * b.im + a.im * b.re};
}

// Row l+m of q(l) (real -> complex SH basis change, e3nn convention),
// including the (-1j)^l global phase. Each row has <= 2 nonzeros.
struct QRow { int ncol; int col[2]; Cpx val[2]; };

__host__ __device__ constexpr QRow qrow(int l, int m) {
    QRow r{};
    double inv2 = 1.0 / csqrt(2.0);
    if (m < 0) {
        r.ncol = 2;
        r.col[0] = l - m;  r.val[0] = Cpx{ inv2, 0.0 };   // l + |m|
        r.col[1] = l + m;  r.val[1] = Cpx{ 0.0, -inv2 };  // l - |m|
    } else if (m == 0) {
        r.ncol = 1;
        r.col[0] = l;      r.val[0] = Cpx{ 1.0, 0.0 };
    } else {
        double s = (m & 1) ? -1.0 : 1.0;  // (-1)^m
        r.ncol = 2;
        r.col[0] = l + m;  r.val[0] = Cpx{ s * inv2, 0.0 };
        r.col[1] = l - m;  r.val[1] = Cpx{ 0.0, s * inv2 };
    }
    // phase (-1j)^l
    Cpx p = (l % 4 == 0) ? Cpx{1, 0} : (l % 4 == 1) ? Cpx{0, -1}
          : (l % 4 == 2) ? Cpx{-1, 0} : Cpx{0, 1};
    for (int t = 0; t < r.ncol; t++) r.val[t] = cmul(p, r.val[t]);
    return r;
}

__host__ __device__ constexpr Meta build_meta() {
    Meta M{};
    M.n = 0;
    int out_off = 0;
    for (int l1 = 0; l1 <= LMAX; l1++) {
        for (int l2 = 0; l2 <= LMAX; l2++) {
            int lo = (l1 > l2) ? (l1 - l2) : (l2 - l1);
            for (int l3 = lo; l3 <= l1 + l2; l3++) {
                if (l3 > LMAX) continue;
                // parity: (-1)^l1 * (-1)^l2 == (-1)^l3  <=>  l1+l2+l3 even
                if (((l1 + l2 + l3) & 1) != 0) continue;

                // real-basis CG tensor:
                // C[a][b][c] = sum_{m1,m2} q1[i,a] q2[k,b] conj(q3[n,c]) * cg
                Cpx Cc[7][7][7] = {};
                for (int m1 = -l1; m1 <= l1; m1++) {
                    for (int m2 = -l2; m2 <= l2; m2++) {
                        int m3 = m1 + m2;
                        if (m3 < -l3 || m3 > l3) continue;
                        double cg = cg_coef(l1, m1, l2, m2, l3, m3);
                        if (cg == 0.0) continue;
                        QRow r1 = qrow(l1, m1);
                        QRow r2 = qrow(l2, m2);
                        QRow r3 = qrow(l3, m3);
                        for (int a = 0; a < r1.ncol; a++)
                        for (int b = 0; b < r2.ncol; b++)
                        for (int c = 0; c < r3.ncol; c++) {
                            Cpx t = cmul(r1.val[a], r2.val[b]);
                            Cpx q3c = Cpx{ r3.val[c].re, -r3.val[c].im };
                            t = cmul(t, q3c);
                            Cc[r1.col[a]][r2.col[b]][r3.col[c]].re += t.re * cg;
                            Cc[r1.col[a]][r2.col[b]][r3.col[c]].im += t.im * cg;
                        }
                    }
                }
                // frobenius-normalize (real part), apply path weight sqrt(2l3+1)
                double nrm2 = 0.0;
                for (int a = 0; a < 2 * l1 + 1; a++)
                for (int b = 0; b < 2 * l2 + 1; b++)
                for (int c = 0; c < 2 * l3 + 1; c++)
                    nrm2 += Cc[a][b][c].re * Cc[a][b][c].re;
                double scale = csqrt((2.0 * l3 + 1.0) / nrm2);

                for (int a = 0; a < 2 * l1 + 1; a++)
                for (int b = 0; b < 2 * l2 + 1; b++)
                for (int c = 0; c < 2 * l3 + 1; c++) {
                    double v = Cc[a][b][c].re * scale;
                    if (v > 1e-12 || v < -1e-12) {
                        if (M.n < MAXE) {
                            M.i1[M.n] = (short)(l1 * l1 + a);
                            M.i2[M.n] = (short)(l2 * l2 + b);
                            M.i3[M.n] = (short)(out_off + c);
                            M.v[M.n]  = (float)v;
                        }
                        M.n++;
                    }
                }
                out_off += 2 * l3 + 1;
            }
        }
    }
    M.out_dim = out_off;
    return M;
}

// ============================================================================
// Compile-time counting sort of the CG entries by output index (i3).
// Each output index belongs to exactly one (l1,l2,l3) path, so grouping by
// i3 lets the kernel finalize + store each output with one live accumulator.
// ============================================================================

struct SortedMeta {
    int   n;
    short i1[MAXE];
    short i2[MAXE];
    float v[MAXE];
    int   start[DIM_OUT + 1];  // entry range [start[j], start[j+1]) feeds out j
};

__host__ __device__ constexpr SortedMeta sort_meta() {
    Meta M = build_meta();
    SortedMeta S{};
    S.n = M.n;
    int cnt[DIM_OUT + 1] = {};
    for (int k = 0; k < M.n; k++) cnt[M.i3[k] + 1]++;
    for (int j = 0; j < DIM_OUT; j++) cnt[j + 1] += cnt[j];
    for (int j = 0; j <= DIM_OUT; j++) S.start[j] = cnt[j];
    int pos[DIM_OUT] = {};
    for (int j = 0; j < DIM_OUT; j++) pos[j] = cnt[j];
    for (int k = 0; k < M.n; k++) {
        int j = M.i3[k];
        int p = pos[j]++;
        S.i1[p] = M.i1[k];
        S.i2[p] = M.i2[k];
        S.v[p]  = M.v[k];
    }
    return S;
}

// Static constexpr member: device code reads it ONLY inside constant
// expressions (template args / constexpr locals) -> never odr-used, never
// materialized in device memory, no --expt-relaxed-constexpr needed.
struct SortedHolder {
    static constexpr SortedMeta S = sort_meta();
};
static_assert(SortedHolder::S.n > 0,     "empty metadata");
static_assert(SortedHolder::S.n <= MAXE, "MAXE too small");

namespace meta_check {
    constexpr Meta HM = build_meta();
    static_assert(HM.out_dim == DIM_OUT, "out_dim mismatch");
}

// ============================================================================
// Front-end (template) unrolled, per-output contraction: for each output j,
// a short FMA chain into ONE accumulator, then an immediate streaming store.
// Keeps the live register set small (inputs + a few temps) so ptxas, under
// the launch-bounds reg cap, must schedule stores throughout the kernel
// instead of a tail burst.
// ============================================================================

template<int E>
__device__ __forceinline__ float fma_entry(const float (&xv)[DIM_IN],
                                           const float (&yv)[DIM_IN],
                                           float a) {
    constexpr int   i = SortedHolder::S.i1[E];
    constexpr int   j = SortedHolder::S.i2[E];
    constexpr float w = SortedHolder::S.v[E];
    return fmaf(w, xv[i] * yv[j], a);
}

template<int J, std::size_t... Es>
__device__ __forceinline__ void emit_output(std::index_sequence<Es...>,
                                            const float (&xv)[DIM_IN],
                                            const float (&yv)[DIM_IN],
                                            float* __restrict__ op) {
    float a = 0.0f;
    ((a = fma_entry<SortedHolder::S.start[J] + (int)Es>(xv, yv, a)), ...);
    __stcs(op + J * CHANNELS, a);   // write-once, never re-read
}

template<std::size_t... Js>
__device__ __forceinline__ void emit_all(std::index_sequence<Js...>,
                                         const float (&xv)[DIM_IN],
                                         const float (&yv)[DIM_IN],
                                         float* __restrict__ op) {
    (emit_output<(int)Js>(
         std::make_index_sequence<(std::size_t)(SortedHolder::S.start[Js + 1]
                                              - SortedHolder::S.start[Js])>{},
         xv, yv, op),
     ...);
}

template<std::size_t... Is>
__device__ __forceinline__ void load_all(std::index_sequence<Is...>,
                                         const float* __restrict__ xp,
                                         const float* __restrict__ yp,
                                         float (&xv)[DIM_IN],
                                         float (&yv)[DIM_IN]) {
    ((xv[Is] = __ldcs(xp + Is * CHANNELS)), ...);
    ((yv[Is] = __ldcs(yp + Is * CHANNELS)), ...);
}

// ============================================================================
// Kernel: one thread per (edge, channel). 512B coalesced rows; zero smem;
// no local memory; CG weights folded into FFMA immediates.
// __launch_bounds__(128, 10): 51-reg cap -> ~40 warps/SM target, and the
// cap enforces store-as-you-go scheduling.
// ============================================================================

__global__ void __launch_bounds__(128, 10)
tp_kernel(const float* __restrict__ x, const float* __restrict__ y,
          float* __restrict__ out) {
    const int n = blockIdx.x;
    const int c = threadIdx.x;

    const float* xp = x + (size_t)n * DIM_IN * CHANNELS + c;
    const float* yp = y + (size_t)n * DIM_IN * CHANNELS + c;

    float xv[DIM_IN], yv[DIM_IN];
    load_all(std::make_index_sequence<DIM_IN>{}, xp, yp, xv, yv);

    float* op = out + (size_t)n * DIM_OUT * CHANNELS + c;
    emit_all(std::make_index_sequence<DIM_OUT>{}, xv, yv, op);
}

// ============================================================================
// Launch
// ============================================================================

extern "C" void kernel_launch(void* const* d_in, const int* in_sizes, int n_in,
                              void* d_out, int out_size) {
    const float* x = (const float*)d_in[0];
    const float* y = (const float*)d_in[1];
    // mu1/mu2/mu3/cg (d_in[2..5]) are fixed mathematical constants baked in
    // at compile time; ignored at runtime.
    float* out = (float*)d_out;

    int n_edges = in_sizes[0] / (DIM_IN * CHANNELS);
    tp_kernel<<<n_edges, CHANNELS>>>(x, y, out);
}